// round 17
// baseline (speedup 1.0000x reference)
#include <cuda_runtime.h>
#include <cuda_fp16.h>
#include <cstdint>

// Problem dims (fixed)
#define Bv 64
#define Hv 128
#define Wv 128
#define Cv 3
#define Nv 10

#define ROWS 32                // output rows per CTA
#define SRR 37                 // staged strip rows (32 + 4 halo + 1 lookahead)
#define PXB 64                 // pixels per CTA
#define WPR 36                 // px-pair words per row (cc 0..71)
#define WST 40                 // word stride per row
#define NT 128                 // 4 warps, one 16-px col tile each

__device__ __forceinline__ void mma_f16(float c[4], const uint32_t a[4],
                                        uint32_t b0, uint32_t b1) {
    asm("mma.sync.aligned.m16n8k16.row.col.f32.f16.f16.f32 "
        "{%0,%1,%2,%3}, {%4,%5,%6,%7}, {%8,%9}, {%0,%1,%2,%3};"
        : "+f"(c[0]), "+f"(c[1]), "+f"(c[2]), "+f"(c[3])
        : "r"(a[0]), "r"(a[1]), "r"(a[2]), "r"(a[3]), "r"(b0), "r"(b1));
}

// out[n][b][c][h][w] = sum_{kh,kw} images[b][h+kh-2][w+kw-2][c] * kernels[b][kh][kw][n]
// fp16 m16n8k16, A = weights [n=16][k=16], B = pixels [k=16][px=8].
// K group G = kh rows (2G: slots 0..7 kw=slot, 2G+1: slots 8..15 kw=slot-8);
// kw>=5 / kh=5 / n>=10 slots carry ZERO WEIGHTS -> pixel operand never masked.
// B fragment = one u32 (adjacent-px fp16 pair, dual shifted strip copies);
// row carry b0<-b1 leaves 1 LDS per tile per strip row, prefetched depth 1.
__global__ __launch_bounds__(NT, 5)
void cdna_mma_kernel(const float* __restrict__ images,
                     const float* __restrict__ kernels,
                     float* __restrict__ out)
{
    __shared__ uint32_t stripA[SRR * WST];   // word j = (px 2j, 2j+1) fp16x2
    __shared__ uint32_t stripB[SRR * WST];   // word j = (px 2j+1, 2j+2) fp16x2
    __shared__ uint32_t Wp[6][4][16];        // [kh][kw-pair][n] fp16x2 (kh=5 zero)

    const int tid  = threadIdx.x;
    const int lane = tid & 31;
    const int wrp  = tid >> 5;         // 0..3: 16-px column tile
    const int g    = lane >> 2;        // 0..7
    const int tg   = lane & 3;         // 0..3

    const int bx = blockIdx.x & 1;     // width half
    const int rt = blockIdx.x >> 1;    // row tile 0..3
    const int c  = blockIdx.y;
    const int b  = blockIdx.z;
    const int r0 = rt * ROWS;
    const int px0 = bx * PXB;

    // ---- stage weight pairs: Wp[kh][t][n] = fp16x2(W[kh][2t][n], W[kh][2t+1][n]) ----
    for (int i = tid; i < 384; i += NT) {
        int kh = i >> 6, rem = i & 63, t = rem >> 4, n = rem & 15;
        int kw0 = 2 * t, kw1 = 2 * t + 1;
        float v0 = 0.0f, v1 = 0.0f;
        if (kh < 5 && n < Nv) {
            if (kw0 < 5) v0 = kernels[(b * 25 + kh * 5 + kw0) * Nv + n];
            if (kw1 < 5) v1 = kernels[(b * 25 + kh * 5 + kw1) * Nv + n];
        }
        __half2 h = __floats2half2_rn(v0, v1);
        (&Wp[0][0][0])[i] = *reinterpret_cast<uint32_t*>(&h);
    }

    // ---- stage fp16 strip (both pair-parities, zero-padded halo) ----
    const float* imgb = images + ((size_t)b * Hv) * (Wv * Cv) + c;
    for (int i = tid; i < SRR * WPR; i += NT) {
        int r = i / WPR, j = i - r * WPR;
        int gh = r0 + r - 2;
        int gw0 = px0 + 2 * j - 2;      // image col of cc=2j
        float f0 = 0.0f, f1 = 0.0f, f2 = 0.0f;
        if (gh >= 0 && gh < Hv) {
            const float* row = imgb + (size_t)gh * Wv * Cv;
            if (gw0     >= 0 && gw0     < Wv) f0 = row[gw0 * Cv];
            if (gw0 + 1 >= 0 && gw0 + 1 < Wv) f1 = row[(gw0 + 1) * Cv];
            if (gw0 + 2 >= 0 && gw0 + 2 < Wv) f2 = row[(gw0 + 2) * Cv];
        }
        __half2 hA = __floats2half2_rn(f0, f1);
        __half2 hB = __floats2half2_rn(f1, f2);
        stripA[r * WST + j] = *reinterpret_cast<uint32_t*>(&hA);
        stripB[r * WST + j] = *reinterpret_cast<uint32_t*>(&hB);
    }
    __syncthreads();

    // ---- A (weight) fragments, resident: wf[G] = (a0,a1,a2,a3) ----
    uint32_t wf[3][4];
    #pragma unroll
    for (int G = 0; G < 3; G++) {
        wf[G][0] = Wp[2 * G][tg][g];
        wf[G][1] = Wp[2 * G][tg][g + 8];
        wf[G][2] = Wp[2 * G + 1][tg][g];
        wf[G][3] = Wp[2 * G + 1][tg][g + 8];
    }

    // ---- per-lane B word pointer: pair start s0 = tilebase + g + 2tg ----
    const int s0 = wrp * 16 + g + 2 * tg;
    const uint32_t* fb = ((s0 & 1) ? stripB : stripA) + (s0 >> 1);
    // tile q=1 is +8 px = +4 words, same parity

    const size_t ns = (size_t)Bv * Cv * Hv * Wv;
    float* outbc = out + (((size_t)b * Cv + c) * Hv + r0) * Wv + px0;

    float acc0[5][4] = {};              // tile 0 ring
    float acc1[5][4] = {};              // tile 1 ring

    uint32_t bc0 = fb[0],        bc1 = fb[4];          // strip row 0
    uint32_t bn0 = fb[WST],      bn1 = fb[WST + 4];    // strip row 1
    const uint32_t* fp = fb + 2 * WST;

    #pragma unroll
    for (int ai = 0; ai < SRR - 1; ai++) {             // 36 iterations
        uint32_t bf0 = 0u, bf1 = 0u;
        if (ai + 2 < SRR) { bf0 = fp[0]; bf1 = fp[4]; }  // prefetch row ai+2
        fp += WST;

        #pragma unroll
        for (int G = 0; G < 3; G++) {
            const int r = ai - 2 * G;
            if (r >= 0 && r < ROWS) {
                const int sl = r % 5;
                mma_f16(acc0[sl], wf[G], bc0, bn0);
                mma_f16(acc1[sl], wf[G], bc1, bn1);
            }
        }

        const int rd = ai - 4;          // completed output row
        if (rd >= 0) {
            const int sl = rd % 5;
            // thread holds px pair (2tg, 2tg+1) for n=g (c0,c1) and n=g+8 (c2,c3)
            float* base = outbc + (size_t)rd * Wv + wrp * 16 + 2 * tg;
            float2 v00 = make_float2(acc0[sl][0], acc0[sl][1]);
            float2 v01 = make_float2(acc1[sl][0], acc1[sl][1]);
            *reinterpret_cast<float2*>(base + (size_t)g * ns)     = v00;
            *reinterpret_cast<float2*>(base + (size_t)g * ns + 8) = v01;
            if (g < 2) {                 // n = 8, 9
                float2 v10 = make_float2(acc0[sl][2], acc0[sl][3]);
                float2 v11 = make_float2(acc1[sl][2], acc1[sl][3]);
                *reinterpret_cast<float2*>(base + (size_t)(g + 8) * ns)     = v10;
                *reinterpret_cast<float2*>(base + (size_t)(g + 8) * ns + 8) = v11;
            }
            #pragma unroll
            for (int q = 0; q < 4; q++) { acc0[sl][q] = 0.0f; acc1[sl][q] = 0.0f; }
        }

        bc0 = bn0; bc1 = bn1;
        bn0 = bf0; bn1 = bf1;
    }
}

extern "C" void kernel_launch(void* const* d_in, const int* in_sizes, int n_in,
                              void* d_out, int out_size)
{
    const float* images  = (const float*)d_in[0];   // [B,H,W,C]
    const float* kernels = (const float*)d_in[1];   // [B,KH,KW,N]
    float* out = (float*)d_out;                     // [N,B,C,H,W]

    dim3 block(NT, 1, 1);
    dim3 grid((Wv / PXB) * (Hv / ROWS), Cv, Bv);   // (8, 3, 64)
    cdna_mma_kernel<<<grid, block>>>(images, kernels, out);
}